// round 1
// baseline (speedup 1.0000x reference)
#include <cuda_runtime.h>

#define NU 8192
#define NC 8192
#define NK 8192
#define D  32

// ---------------- scratch (static __device__, no allocation) ----------------
__device__ float g_T0[NU * D];        // dinv_uu ⊙ (X_U @ weight_s)
__device__ float g_T1[NC * D];        // dinv_cc ⊙ (X_C @ weight_s)
__device__ float g_T2[NU * D];        // dc ⊙ ((X_U @ proj_u) @ weight_c)
__device__ float g_c1[NC * D];        // node_embed_c1
__device__ float g_c2[NC * D];        // node_embed_c2
__device__ float g_dinv_uu[NU];
__device__ float g_dinv_cc[NC];
__device__ float g_du[NU];
__device__ float g_dc[NC];
__device__ float g_colpart[512 * NC]; // per-block colsum partials for adj_uc
__device__ float g_W2[D * D];         // proj_u @ weight_c

// ---------------- packed f32x2 helpers ----------------
__device__ __forceinline__ unsigned long long ffma2(
    unsigned long long a, unsigned long long b, unsigned long long c) {
    unsigned long long d;
    asm("fma.rn.f32x2 %0, %1, %2, %3;" : "=l"(d) : "l"(a), "l"(b), "l"(c));
    return d;
}
__device__ __forceinline__ unsigned long long bcast2(float x) {
    unsigned long long r;
    asm("mov.b64 %0, {%1, %1};" : "=l"(r) : "f"(x));
    return r;
}
__device__ __forceinline__ float lo32(unsigned long long v) {
    return __uint_as_float((unsigned)(v & 0xffffffffull));
}
__device__ __forceinline__ float hi32(unsigned long long v) {
    return __uint_as_float((unsigned)(v >> 32));
}

// ---------------- tiny: W2 = proj_u @ weight_c ----------------
__global__ void k_w2(const float* __restrict__ proj_u,
                     const float* __restrict__ weight_c) {
    int i = threadIdx.x >> 5;
    int j = threadIdx.x & 31;
    float s = 0.f;
#pragma unroll
    for (int k = 0; k < 32; k++) s += proj_u[i * 32 + k] * weight_c[k * 32 + j];
    g_W2[i * 32 + j] = s;
}

// ---------------- rowsums for adj_uu / adj_cc -> rsqrt(1 + rowsum) ----------------
__global__ void k_rowsum(const float* __restrict__ adj_uu,
                         const float* __restrict__ adj_cc) {
    int row = blockIdx.x;
    const float* A = (blockIdx.y == 0) ? adj_uu : adj_cc;
    float* out = (blockIdx.y == 0) ? g_dinv_uu : g_dinv_cc;

    const float4* p = (const float4*)(A + (size_t)row * NK);
    float s = 0.f;
#pragma unroll
    for (int i = threadIdx.x; i < NK / 4; i += 256) {
        float4 v = p[i];
        s += (v.x + v.y) + (v.z + v.w);
    }
#pragma unroll
    for (int o = 16; o; o >>= 1) s += __shfl_xor_sync(0xffffffffu, s, o);
    __shared__ float sm[8];
    if ((threadIdx.x & 31) == 0) sm[threadIdx.x >> 5] = s;
    __syncthreads();
    if (threadIdx.x == 0) {
        float t = 0.f;
#pragma unroll
        for (int i = 0; i < 8; i++) t += sm[i];
        out[row] = rsqrtf(1.0f + t);
    }
}

// ---------------- adj_uc: rowsums -> du, colsum partials -> g_colpart ----------------
// 512 blocks x 16 rows each; one full-width pass over the matrix.
__global__ void k_uc_sums(const float* __restrict__ adj_uc) {
    int tid = threadIdx.x;  // 256
    int m0 = blockIdx.x * 16;
    float4 colacc[8];
#pragma unroll
    for (int i = 0; i < 8; i++) colacc[i] = make_float4(0.f, 0.f, 0.f, 0.f);
    __shared__ float sm[8];

    for (int r = 0; r < 16; r++) {
        const float4* p = (const float4*)(adj_uc + (size_t)(m0 + r) * NK);
        float rs = 0.f;
#pragma unroll
        for (int i = 0; i < 8; i++) {
            float4 v = p[tid + i * 256];
            colacc[i].x += v.x; colacc[i].y += v.y;
            colacc[i].z += v.z; colacc[i].w += v.w;
            rs += (v.x + v.y) + (v.z + v.w);
        }
#pragma unroll
        for (int o = 16; o; o >>= 1) rs += __shfl_xor_sync(0xffffffffu, rs, o);
        __syncthreads();  // protect sm reuse across iterations
        if ((tid & 31) == 0) sm[tid >> 5] = rs;
        __syncthreads();
        if (tid == 0) {
            float t = 0.f;
#pragma unroll
            for (int i = 0; i < 8; i++) t += sm[i];
            g_du[m0 + r] = rsqrtf(t);  // no +1 in gcn_c
        }
    }
    float4* cp = (float4*)(g_colpart + (size_t)blockIdx.x * NC);
#pragma unroll
    for (int i = 0; i < 8; i++) cp[tid + i * 256] = colacc[i];
}

// ---------------- deterministic colsum reduce -> dc ----------------
__global__ void k_dc() {
    int c = blockIdx.x * 256 + threadIdx.x;  // 32 blocks
    float s = 0.f;
    for (int r = 0; r < 512; r++) s += g_colpart[(size_t)r * NC + c];
    g_dc[c] = rsqrtf(s);  // no +1 in gcn_c
}

// ---------------- scaled supports T0/T1/T2 ----------------
__global__ void k_support(const float* __restrict__ X_U,
                          const float* __restrict__ X_C,
                          const float* __restrict__ weight_s) {
    __shared__ float Ws[1024];
    int which = blockIdx.y;
    int tid = threadIdx.x;  // 256
    if (which == 2) {
        for (int i = tid; i < 1024; i += 256) Ws[i] = g_W2[i];
    } else {
        for (int i = tid; i < 1024; i += 256) Ws[i] = weight_s[i];
    }
    __syncthreads();

    int row = blockIdx.x * 8 + (tid >> 5);
    int c = tid & 31;
    const float* X = (which == 1) ? X_C : X_U;
    const float* xr = X + (size_t)row * 32;
    float s = 0.f;
#pragma unroll
    for (int k = 0; k < 32; k++) s += xr[k] * Ws[k * 32 + c];

    float scale;
    float* T;
    if (which == 0)      { scale = g_dinv_uu[row]; T = g_T0; }
    else if (which == 1) { scale = g_dinv_cc[row]; T = g_T1; }
    else                 { scale = g_dc[row];      T = g_T2; }
    T[(size_t)row * 32 + c] = scale * s;
}

// ---------------- fused 3-way SpMM: out = rowscale ⊙ (A @ T) ----------------
// BM=32 rows/block, BK=32, 128 threads: thread -> (row r = tid>>2, colgroup g = tid&3, 8 cols)
// grid = 768 (3 matrices x 256 row-blocks) => all blocks resident, ~5/SM.
#define BM 32
#define BK 32
#define APITCH 36  // pad: conflict-free + 16B-aligned stores

__global__ void __launch_bounds__(128) k_spmm(
    const float* __restrict__ adj_uu, const float* __restrict__ adj_cc,
    const float* __restrict__ adj_uc, float* __restrict__ out_u) {
    int mat = blockIdx.x >> 8;
    int mb  = blockIdx.x & 255;

    const float* A;
    const float* T;
    const float* rowscale;
    float* out;
    if (mat == 0)      { A = adj_uu; T = g_T0; rowscale = g_dinv_uu; out = out_u; }
    else if (mat == 1) { A = adj_cc; T = g_T1; rowscale = g_dinv_cc; out = g_c1; }
    else               { A = adj_uc; T = g_T2; rowscale = g_du;      out = g_c2; }

    __shared__ float As[BM * APITCH];  // 4.6 KB
    __shared__ float Bs[BK * 32];      // 4 KB

    int tid = threadIdx.x;
    int r = tid >> 2;   // 0..31
    int g = tid & 3;    // 8 cols each

    int m0 = mb * BM;
    const float* Abase = A + (size_t)m0 * NK;

    unsigned long long acc0 = 0, acc1 = 0, acc2 = 0, acc3 = 0;

    for (int k0 = 0; k0 < NK; k0 += BK) {
        // stage A tile (32x32) and B tile (32x32), coalesced float4
        {
            int f = tid;
#pragma unroll
            for (int it = 0; it < 2; it++, f += 128) {
                int rr = f >> 3, kq = f & 7;
                float4 v = *(const float4*)(Abase + (size_t)rr * NK + k0 + kq * 4);
                *(float4*)(As + rr * APITCH + kq * 4) = v;
            }
            f = tid;
#pragma unroll
            for (int it = 0; it < 2; it++, f += 128) {
                int kk = f >> 3, cq = f & 7;
                *(float4*)(Bs + kk * 32 + cq * 4) =
                    *(const float4*)(T + (size_t)(k0 + kk) * 32 + cq * 4);
            }
        }
        __syncthreads();

        const float* arow = As + r * APITCH;
        const float* bcol = Bs + g * 8;
#pragma unroll
        for (int kk = 0; kk < BK; kk++) {
            unsigned long long a2 = bcast2(arow[kk]);
            ulonglong2 b01 = *(const ulonglong2*)(bcol + kk * 32);
            ulonglong2 b23 = *(const ulonglong2*)(bcol + kk * 32 + 4);
            acc0 = ffma2(a2, b01.x, acc0);
            acc1 = ffma2(a2, b01.y, acc1);
            acc2 = ffma2(a2, b23.x, acc2);
            acc3 = ffma2(a2, b23.y, acc3);
        }
        __syncthreads();
    }

    float sc = rowscale[m0 + r];
    float4 o0 = make_float4(sc * lo32(acc0), sc * hi32(acc0),
                            sc * lo32(acc1), sc * hi32(acc1));
    float4 o1 = make_float4(sc * lo32(acc2), sc * hi32(acc2),
                            sc * lo32(acc3), sc * hi32(acc3));
    float* orow = out + (size_t)(m0 + r) * 32 + g * 8;
    *(float4*)(orow) = o0;
    *(float4*)(orow + 4) = o1;
}

// ---------------- attention + softmax + outputs ----------------
__global__ void k_attn(const float* __restrict__ X_C,
                       const float* __restrict__ W_lin,
                       const float* __restrict__ a_vec,
                       float* __restrict__ out) {
    __shared__ float Ws[64 * 32];
    __shared__ float av[32];
    int tid = threadIdx.x;  // 256
    for (int i = tid; i < 2048; i += 256) Ws[i] = W_lin[i];
    if (tid < 32) av[tid] = a_vec[tid];
    __syncthreads();

    int lane = tid & 31;
    int row = blockIdx.x * 8 + (tid >> 5);

    float c1v = g_c1[(size_t)row * 32 + lane];
    float c2v = g_c2[(size_t)row * 32 + lane];
    float xcv = X_C[(size_t)row * 32 + lane];

    float h1 = 0.f, h2 = 0.f;
#pragma unroll
    for (int k = 0; k < 32; k++) {
        float u1 = __shfl_sync(0xffffffffu, c1v, k);
        float u2 = __shfl_sync(0xffffffffu, c2v, k);
        float w0 = Ws[k * 32 + lane];
        h1 = fmaf(u1, w0, h1);
        h2 = fmaf(u2, w0, h2);
    }
#pragma unroll
    for (int k = 0; k < 32; k++) {
        float ux = __shfl_sync(0xffffffffu, xcv, k);
        float w1 = Ws[(32 + k) * 32 + lane];
        h1 = fmaf(ux, w1, h1);
        h2 = fmaf(ux, w1, h2);
    }
    float t1 = fmaxf(h1, 0.f) * av[lane];
    float t2 = fmaxf(h2, 0.f) * av[lane];
#pragma unroll
    for (int o = 16; o; o >>= 1) {
        t1 += __shfl_xor_sync(0xffffffffu, t1, o);
        t2 += __shfl_xor_sync(0xffffffffu, t2, o);
    }
    float m = fmaxf(t1, t2);
    float e1 = expf(t1 - m), e2 = expf(t2 - m);
    float inv = 1.f / (e1 + e2);
    float yc = (e1 * inv) * c1v;
    float yu = (e2 * inv) * c2v;

    size_t idx = (size_t)row * 32 + lane;
    out[262144 + idx] = yc + yu;  // node_embed_c
    out[524288 + idx] = yc;       // Y_c
    out[786432 + idx] = yu;       // Y_u
}

// ---------------- launch ----------------
extern "C" void kernel_launch(void* const* d_in, const int* in_sizes, int n_in,
                              void* d_out, int out_size) {
    const float* X_U      = (const float*)d_in[0];
    const float* X_C      = (const float*)d_in[1];
    const float* adj_uu   = (const float*)d_in[2];
    const float* adj_uc   = (const float*)d_in[3];
    const float* adj_cc   = (const float*)d_in[4];
    const float* weight_s = (const float*)d_in[5];
    const float* proj_u   = (const float*)d_in[6];
    // d_in[7] = proj_c (unused in forward math)
    const float* weight_c = (const float*)d_in[8];
    const float* W_lin    = (const float*)d_in[9];
    const float* a_vec    = (const float*)d_in[10];
    float* out = (float*)d_out;

    k_w2<<<1, 1024>>>(proj_u, weight_c);
    k_rowsum<<<dim3(8192, 2), 256>>>(adj_uu, adj_cc);
    k_uc_sums<<<512, 256>>>(adj_uc);
    k_dc<<<32, 256>>>();
    k_support<<<dim3(1024, 3), 256>>>(X_U, X_C, weight_s);
    k_spmm<<<768, 128>>>(adj_uu, adj_cc, adj_uc, out);
    k_attn<<<1024, 256>>>(X_C, W_lin, a_vec, out);
}